// round 7
// baseline (speedup 1.0000x reference)
#include <cuda_runtime.h>
#include <cstdint>

#define B_SZ 512
#define D_SZ 1024
#define P_SZ 16
#define N_SZ 128
#define ALPHA_F 0.8f
#define NROWS 145                 // row 0 = tgt, 1..16 = rel, 17..144 = irr
#define SPLIT 4
#define NBLOCKS (B_SZ * SPLIT)    // 2048
#define TPB 128
#define NWARPS 4
#define DEPTH 3
#define ROW_BYTES 4096            // 1024 fp32

// dynamic smem layout: [buffers: NWARPS*DEPTH*ROW_BYTES][mbarriers: NWARPS*DEPTH*8]
#define SMEM_BUF_BYTES (NWARPS * DEPTH * ROW_BYTES)     // 49152
#define SMEM_TOTAL     (SMEM_BUF_BYTES + NWARPS * DEPTH * 8 + 16)

__device__ float g_pos[NBLOCKS];
__device__ float g_neg[NBLOCKS];
__device__ float g_diag[B_SZ];
__device__ unsigned int g_count = 0;

__device__ __forceinline__ uint32_t smem_u32(const void* p) {
    uint32_t a;
    asm("{ .reg .u64 t; cvta.to.shared.u64 t, %1; cvt.u32.u64 %0, t; }"
        : "=r"(a) : "l"(p));
    return a;
}
__device__ __forceinline__ void mbar_init(uint32_t mbar, uint32_t count) {
    asm volatile("mbarrier.init.shared.b64 [%0], %1;" :: "r"(mbar), "r"(count) : "memory");
}
__device__ __forceinline__ void mbar_expect_tx(uint32_t mbar, uint32_t bytes) {
    asm volatile("mbarrier.arrive.expect_tx.shared.b64 _, [%0], %1;"
                 :: "r"(mbar), "r"(bytes) : "memory");
}
__device__ __forceinline__ void tma_row(uint32_t smem_dst, const float* gmem_src, uint32_t mbar) {
    asm volatile("cp.async.bulk.shared::cta.global.mbarrier::complete_tx::bytes "
                 "[%0], [%1], %2, [%3];"
                 :: "r"(smem_dst), "l"(gmem_src), "r"((uint32_t)ROW_BYTES), "r"(mbar)
                 : "memory");
}
__device__ __forceinline__ void mbar_wait(uint32_t mbar, uint32_t parity) {
    uint32_t done;
    asm volatile(
        "{\n\t.reg .pred p;\n\t"
        "mbarrier.try_wait.parity.acquire.cta.shared::cta.b64 p, [%1], %2;\n\t"
        "selp.b32 %0, 1, 0, p;\n\t}"
        : "=r"(done) : "r"(mbar), "r"(parity) : "memory");
    if (!done) {
        asm volatile(
            "{\n\t.reg .pred P1;\n\t"
            "W_%=:\n\t"
            "mbarrier.try_wait.parity.acquire.cta.shared::cta.b64 P1, [%0], %1, 0x989680;\n\t"
            "@P1 bra.uni D_%=;\n\t"
            "bra.uni W_%=;\n\t"
            "D_%=:\n\t}"
            :: "r"(mbar), "r"(parity) : "memory");
    }
}

__device__ __forceinline__ const float*
row_ptr(const float* __restrict__ tgt, const float* __restrict__ rel,
        const float* __restrict__ irr, int b, int r)
{
    if (r == 0)         return tgt + (size_t)b * D_SZ;
    else if (r <= P_SZ) return rel + ((size_t)b * P_SZ + (r - 1)) * D_SZ;
    else                return irr + ((size_t)b * N_SZ + (r - 1 - P_SZ)) * D_SZ;
}

__global__ void __launch_bounds__(TPB)
contrastive_loss_kernel(const float* __restrict__ src,
                        const float* __restrict__ tgt,
                        const float* __restrict__ rel,
                        const float* __restrict__ irr,
                        float* __restrict__ out)
{
    extern __shared__ __align__(16) char dsm[];
    __shared__ float s_pos[NWARPS], s_neg[NWARPS];
    __shared__ int   s_last;

    const int blk  = blockIdx.x;
    const int b    = blk >> 2;            // batch row
    const int s    = blk & 3;             // split index
    const int tid  = threadIdx.x;
    const int wid  = tid >> 5;
    const int lane = tid & 31;

    const uint32_t dsm_base  = smem_u32(dsm);
    const uint32_t mbar_base = dsm_base + SMEM_BUF_BYTES;
    const uint32_t my_buf0   = dsm_base + (uint32_t)(wid * DEPTH) * ROW_BYTES;
    const uint32_t my_mbar0  = mbar_base + (uint32_t)(wid * DEPTH) * 8;

    // ---- per-warp mbarrier init ----
    if (lane == 0) {
        #pragma unroll
        for (int k = 0; k < DEPTH; k++) mbar_init(my_mbar0 + k * 8, 1);
        asm volatile("fence.mbarrier_init.release.cluster;" ::: "memory");
    }
    __syncwarp();

    // ---- contiguous per-warp chunk of this block's slice ----
    const int r0 = (s * NROWS) / SPLIT;
    const int r1 = ((s + 1) * NROWS) / SPLIT;
    const int sl = r1 - r0;
    const int cstart = r0 + (wid * sl) / NWARPS;
    const int cend   = r0 + ((wid + 1) * sl) / NWARPS;
    const int clen   = cend - cstart;

    // ---- prime pipeline (depth 3) before the src load ----
    if (lane == 0) {
        #pragma unroll
        for (int k = 0; k < DEPTH; k++) {
            if (k < clen) {
                mbar_expect_tx(my_mbar0 + k * 8, ROW_BYTES);
                tma_row(my_buf0 + k * ROW_BYTES, row_ptr(tgt, rel, irr, b, cstart + k),
                        my_mbar0 + k * 8);
            }
        }
    }

    // ---- src row into registers (L2-hot); warp-local norm ----
    const float4* srcv = reinterpret_cast<const float4*>(src + (size_t)b * D_SZ);
    float4 sreg[8];
    float ss = 0.f;
    #pragma unroll
    for (int j = 0; j < 8; j++) {
        sreg[j] = __ldg(&srcv[j * 32 + lane]);
        ss += sreg[j].x * sreg[j].x + sreg[j].y * sreg[j].y
            + sreg[j].z * sreg[j].z + sreg[j].w * sreg[j].w;
    }
    #pragma unroll
    for (int o = 16; o > 0; o >>= 1) ss += __shfl_xor_sync(0xFFFFFFFFu, ss, o);
    const float inv_src = rsqrtf(fmaxf(ss, 1e-24f));

    float pos_acc = 0.f, neg_acc = 0.f, diag = 0.f;

    for (int i = 0; i < clen; i++) {
        const int q = i / DEPTH;
        const int k = i - q * DEPTH;
        const uint32_t mb = my_mbar0 + k * 8;
        const uint32_t sb = my_buf0 + k * ROW_BYTES;

        mbar_wait(mb, (uint32_t)q & 1u);

        const float4* rv = reinterpret_cast<const float4*>(dsm) +
                           (size_t)(wid * DEPTH + k) * (ROW_BYTES / 16);
        float dot = 0.f, rss = 0.f;
        #pragma unroll
        for (int j = 0; j < 8; j++) {
            float4 v = rv[j * 32 + lane];
            dot += v.x * sreg[j].x + v.y * sreg[j].y + v.z * sreg[j].z + v.w * sreg[j].w;
            rss += v.x * v.x + v.y * v.y + v.z * v.z + v.w * v.w;
        }

        // refill stage k with row i+DEPTH (warp is convergent: all lanes done reading)
        if (lane == 0 && i + DEPTH < clen) {
            mbar_expect_tx(mb, ROW_BYTES);
            tma_row(sb, row_ptr(tgt, rel, irr, b, cstart + i + DEPTH), mb);
        }

        // reduce while 2-3 rows stream underneath
        #pragma unroll
        for (int o = 16; o > 0; o >>= 1) {
            dot += __shfl_xor_sync(0xFFFFFFFFu, dot, o);
            rss += __shfl_xor_sync(0xFFFFFFFFu, rss, o);
        }
        if (lane == 0) {
            const int r = cstart + i;
            float c = dot * inv_src * rsqrtf(fmaxf(rss, 1e-24f));
            if (r == 0)            diag = c;
            else if (r <= P_SZ)    pos_acc += expf(c);
            else                   neg_acc += expf(c);
        }
    }

    if (lane == 0) { s_pos[wid] = pos_acc; s_neg[wid] = neg_acc; }
    __syncthreads();

    if (tid == 0) {
        g_pos[blk] = s_pos[0] + s_pos[1] + s_pos[2] + s_pos[3];
        g_neg[blk] = s_neg[0] + s_neg[1] + s_neg[2] + s_neg[3];
        if (s == 0) g_diag[b] = diag;   // block s=0 warp 0 owns row 0; tid0 = its lane0

        unsigned int old;
        asm volatile("atom.acq_rel.gpu.global.add.u32 %0, [%1], %2;"
                     : "=r"(old)
                     : "l"(&g_count), "r"(1u)
                     : "memory");
        s_last = (old == NBLOCKS - 1);
    }
    __syncthreads();

    // ---- last block computes the final loss (fused) ----
    if (s_last) {
        float acc = 0.f;
        #pragma unroll
        for (int it = 0; it < B_SZ / TPB; it++) {
            int bb = it * TPB + tid;
            float ps = 0.f, ns = 0.f;
            #pragma unroll
            for (int kk = 0; kk < SPLIT; kk++) {
                ps += g_pos[bb * SPLIT + kk];
                ns += g_neg[bb * SPLIT + kk];
            }
            float pos_score = 1.f + ps;
            float lp = logf(pos_score);
            float ln = logf(pos_score + ns);
            acc += -(ALPHA_F * g_diag[bb] + (1.f - ALPHA_F) * (lp - ln));
        }
        #pragma unroll
        for (int o = 16; o > 0; o >>= 1) acc += __shfl_xor_sync(0xFFFFFFFFu, acc, o);
        if (lane == 0) s_pos[wid] = acc;
        __syncthreads();
        if (tid == 0) {
            out[0] = (s_pos[0] + s_pos[1] + s_pos[2] + s_pos[3]) * (1.0f / (float)B_SZ);
            g_count = 0;                // reset for next graph replay
        }
    }
}

extern "C" void kernel_launch(void* const* d_in, const int* in_sizes, int n_in,
                              void* d_out, int out_size)
{
    const float* src = (const float*)d_in[0];   // [B, D]
    const float* tgt = (const float*)d_in[1];   // [B, D]
    const float* rel = (const float*)d_in[2];   // [B, P, D]
    const float* irr = (const float*)d_in[3];   // [B, N, D]
    float* out = (float*)d_out;

    cudaFuncSetAttribute(contrastive_loss_kernel,
                         cudaFuncAttributeMaxDynamicSharedMemorySize, SMEM_TOTAL);
    contrastive_loss_kernel<<<NBLOCKS, TPB, SMEM_TOTAL>>>(src, tgt, rel, irr, out);
}